// round 17
// baseline (speedup 1.0000x reference)
#include <cuda_runtime.h>
#include <math.h>

#define B_   128
#define S_   512
#define T_   36
#define STARTT 34
#define ENDT   35
#define NTHREADS 320

// dynamic smem layout (floats):
//  [0, 18432)        exp(feats) (S*T)   (reused as finalize scratch)
//  [18432, 19728)    raw transitions (36*36)
//  [19728, 20496)    ping-pong buffers: 8 chains x 96 (2 bufs x 48, slots 34..47 zero)
//  [20496, 20816)    meet vectors: 8 x 40  (chain c output at MV + 40c, 34 used)
//  [20816, 20848)    RD: ints [0..9] len partials, floats [10..11] gold parts,
//                    [12] gold total, ints [16..23] per-chain Ks
#define EF  0
#define TR  18432
#define PP  19728
#define MV  20496
#define RD  20816
#define SMEM_FLOATS 20848
#define SMEM_BYTES  (SMEM_FLOATS * 4)

typedef unsigned long long ull;

__device__ float g_partial[B_];
__device__ int   g_count = 0;

__device__ __forceinline__ ull ffma2(ull a, ull b, ull c) {
    ull d;
    asm("fma.rn.f32x2 %0, %1, %2, %3;" : "=l"(d) : "l"(a), "l"(b), "l"(c));
    return d;
}
__device__ __forceinline__ ull fadd2(ull a, ull b) {
    ull d;
    asm("add.rn.f32x2 %0, %1, %2;" : "=l"(d) : "l"(a), "l"(b));
    return d;
}
__device__ __forceinline__ ull pack2(float lo, float hi) {
    ull d;
    asm("mov.b64 %0, {%1, %2};" : "=l"(d) : "f"(lo), "f"(hi));
    return d;
}
__device__ __forceinline__ void unpack2(ull v, float& lo, float& hi) {
    asm("mov.b64 {%0, %1}, %2;" : "=f"(lo), "=f"(hi) : "l"(v));
}

// Full 34-dot for this lane's column pair, cross-packed (round-3/5 proven body).
// sbuf must be zero-padded through slot 35. Returns V[0].x (packed v0,v1) for renorm.
__device__ __forceinline__ void matvec34(const float* __restrict__ sbuf,
                                         const ull* __restrict__ Ea,
                                         const ull* __restrict__ Eb,
                                         float& r0, float& r1, ull& first)
{
    const ulonglong2* Vp = (const ulonglong2*)sbuf;
    ulonglong2 V[9];
    #pragma unroll
    for (int q = 0; q < 9; q++) V[q] = Vp[q];

    ull accA[3] = {0, 0, 0}, accB[3] = {0, 0, 0};
    #pragma unroll
    for (int m = 0; m < 17; m++) {
        const ull pm = (m & 1) ? V[m >> 1].y : V[m >> 1].x;
        accA[m % 3] = ffma2(pm, Ea[m], accA[m % 3]);
        accB[m % 3] = ffma2(pm, Eb[m], accB[m % 3]);
    }
    const ull rA = fadd2(fadd2(accA[0], accA[1]), accA[2]);
    const ull rB = fadd2(fadd2(accB[0], accB[1]), accB[2]);
    float a0, a1, b0, b1;
    unpack2(rA, a0, a1);
    unpack2(rB, b0, b1);
    r0 = a0 + b1;
    r1 = a1 + b0;
    first = V[0].x;
}

// ---- one fwd step; REN = power-of-two renorm (every 2nd step) ----
#define FWD_ONE(BUF, REN, TT) do {                                            \
    const float2 ef2 = *(const float2*)(sh + EF + (TT) * T_ + j0);            \
    float r0, r1; ull f0;                                                     \
    matvec34(pb + (BUF) * 48, EA, EB, r0, r1, f0);                            \
    float sx = ef2.x, sy = ef2.y;                                             \
    if (REN) {                                                                \
        const unsigned p0 = (unsigned)(f0 & 0xFFFFFFFFull);                   \
        int k = (int)((p0 >> 23) & 0xFF) - 127;                               \
        k = max(-120, min(120, k));                                           \
        Ks += k;                                                              \
        const float sc = __int_as_float((unsigned)(127 - k) << 23);           \
        sx *= sc; sy *= sc;                                                   \
    }                                                                         \
    pc.x = r0 * sx;  pc.y = r1 * sy;                                          \
    if (lane < 17) *(float2*)(pb + ((BUF) ^ 1) * 48 + j0) = pc;               \
    __syncwarp();                                                             \
} while (0)

// ---- one bwd step; ef2 holds ef_t (prefetched), reloads for t-1 ----
#define BWD_ONE(BUF, REN, TT) do {                                            \
    float2 q; q.x = bc.x * ef2.x;  q.y = bc.y * ef2.y;                        \
    if (lane < 17) *(float2*)(wb + (BUF) * 48 + j0) = q;                      \
    __syncwarp();                                                             \
    ef2 = *(const float2*)(sh + EF + ((TT) - 1) * T_ + j0);                   \
    float r0, r1; ull f0;                                                     \
    matvec34(wb + (BUF) * 48, TA, TB, r0, r1, f0);                            \
    if (REN) {                                                                \
        const unsigned p0 = (unsigned)(f0 & 0xFFFFFFFFull);                   \
        int k = (int)((p0 >> 23) & 0xFF) - 127;                               \
        k = max(-120, min(120, k));                                           \
        Ks += k;                                                              \
        const float sc = __int_as_float((unsigned)(127 - k) << 23);           \
        bc.x = r0 * sc;  bc.y = r1 * sc;                                      \
    } else {                                                                  \
        bc.x = r0;  bc.y = r1;                                                \
    }                                                                         \
} while (0)

// Forward chain: p_t[j] = ef_t[j] * sum_i p_{t-1}[i] E[i][j], t = tlo..thi.
__device__ __forceinline__ int run_fwd_chain(const float* __restrict__ sh,
                                             float* __restrict__ pb,
                                             float* __restrict__ outv,
                                             int lane, int j0, int j1,
                                             float2 pc, int tlo, int thi)
{
    // cross-packed columns: EA[m]=(E[2m][j0],E[2m+1][j1]) EB[m]=(E[2m][j1],E[2m+1][j0])
    ull EA[17], EB[17];
    #pragma unroll
    for (int m = 0; m < 17; m++) {
        const float t00 = __expf(sh[TR + (2 * m)     * T_ + j0]);
        const float t01 = __expf(sh[TR + (2 * m)     * T_ + j1]);
        const float t10 = __expf(sh[TR + (2 * m + 1) * T_ + j0]);
        const float t11 = __expf(sh[TR + (2 * m + 1) * T_ + j1]);
        EA[m] = pack2(t00, t11);
        EB[m] = pack2(t01, t10);
    }
    if (lane < 17) *(float2*)(pb + j0) = pc;
    __syncwarp();

    int Ks = 0;
    int t = tlo;
    while (t + 1 <= thi) { FWD_ONE(0, true, t); FWD_ONE(1, false, t + 1); t += 2; }
    if (t <= thi) { FWD_ONE(0, true, t); }
    if (lane < 17) *(float2*)(outv + j0) = pc;
    return Ks;
}

// Backward chain: y_{t-1}[i] = sum_j E[i][j] ef_t[j] y_t[j], t = thi down to tloex+1.
__device__ __forceinline__ int run_bwd_chain(const float* __restrict__ sh,
                                             float* __restrict__ wb,
                                             float* __restrict__ outv,
                                             int lane, int j0, int j1,
                                             float2 bc, int tloex, int thi)
{
    // cross-packed rows: TA[m]=(E[j0][2m],E[j1][2m+1]) TB[m]=(E[j1][2m],E[j0][2m+1])
    ull TA[17], TB[17];
    #pragma unroll
    for (int m = 0; m < 17; m++) {
        const float t00 = __expf(sh[TR + j0 * T_ + (2 * m)]);
        const float t01 = __expf(sh[TR + j0 * T_ + (2 * m + 1)]);
        const float t10 = __expf(sh[TR + j1 * T_ + (2 * m)]);
        const float t11 = __expf(sh[TR + j1 * T_ + (2 * m + 1)]);
        TA[m] = pack2(t00, t11);
        TB[m] = pack2(t10, t01);
    }
    float2 ef2 = *(const float2*)(sh + EF + thi * T_ + j0);

    int Ks = 0;
    int t = thi;
    while (t - 1 > tloex) { BWD_ONE(0, true, t); BWD_ONE(1, false, t - 1); t -= 2; }
    if (t > tloex) { BWD_ONE(0, true, t); }
    if (lane < 17) *(float2*)(outv + j0) = bc;
    return Ks;
}

__global__ void __launch_bounds__(NTHREADS, 1)
crf_kernel(const float* __restrict__ feats,
           const float* __restrict__ transitions,
           const int*   __restrict__ mask,
           const int*   __restrict__ tags,
           float*       __restrict__ out)
{
    extern __shared__ float sh[];
    const int tid  = threadIdx.x;
    const int lane = tid & 31;
    const int wid  = tid >> 5;
    const int b    = blockIdx.x;

    // ---- stage exp(feats[b]) (72KB) + raw transitions into smem, coalesced ----
    {
        const float4* fsrc = (const float4*)(feats + (size_t)b * (S_ * T_));
        float4* fdst = (float4*)(sh + EF);
        for (int i = tid; i < (S_ * T_ / 4); i += NTHREADS) {
            float4 v = fsrc[i];
            v.x = __expf(v.x); v.y = __expf(v.y);
            v.z = __expf(v.z); v.w = __expf(v.w);
            fdst[i] = v;
        }
        const float4* tsrc = (const float4*)transitions;
        float4* tdst = (float4*)(sh + TR);
        for (int i = tid; i < (T_ * T_ / 4); i += NTHREADS)
            tdst[i] = tsrc[i];
        // zero-pad slots 34..47 of all 16 ping-pong buffers (never rewritten)
        if (tid < 224) {
            const int c = tid / 28, r = tid % 28;
            const int bf = r / 14, s = r % 14;
            sh[PP + 96 * c + 48 * bf + 34 + s] = 0.0f;
        }
    }

    // ---- sequence length (mask is a contiguous prefix) ----
    int lsum = 0;
    {
        const int* mrow = mask + b * S_;
        for (int i = tid; i < S_; i += NTHREADS) lsum += mrow[i];
    }
    #pragma unroll
    for (int off = 16; off > 0; off >>= 1)
        lsum += __shfl_xor_sync(0xFFFFFFFFu, lsum, off);
    if (lane == 0) ((int*)(sh + RD))[wid] = lsum;
    __syncthreads();
    int len = 0;
    #pragma unroll
    for (int i = 0; i < 10; i++) len += ((const int*)(sh + RD))[i];
    const int n1 = len / 5;            // A = [0, n1]
    const int n2 = (2 * len) / 5;      // B = (n1, n2]
    const int n3 = (3 * len) / 5;      // C = (n2, n3]
    const int n4 = (4 * len) / 5;      // D = (n3, n4],  E = (n4, len)

    const int l  = (lane < 17) ? lane : 16;   // pad lanes duplicate pair 16
    const int j0 = 2 * l, j1 = 2 * l + 1;

    if (wid < 8) {
        // ===== eight independent single-warp chains (syncwarp-only; no named bars) =====
        float* pb   = sh + PP + 96 * wid;
        float* outv = sh + MV + 40 * wid;
        int Ks;
        if (wid == 0) {
            // alpha over A: t = 1..n1
            float2 pinit;
            pinit.x = sh[EF + j0] * __expf(sh[TR + STARTT * T_ + j0]);
            pinit.y = sh[EF + j1] * __expf(sh[TR + STARTT * T_ + j1]);
            Ks = run_fwd_chain(sh, pb, outv, lane, j0, j1, pinit, 1, n1);
        } else if (wid == 1) {
            Ks = run_fwd_chain(sh, pb, outv, lane, j0, j1,      // a_B
                               make_float2(1.f, 1.f), n1 + 1, n2);
        } else if (wid == 2) {
            Ks = run_bwd_chain(sh, pb, outv, lane, j0, j1,      // b_B
                               make_float2(1.f, 1.f), n1, n2);
        } else if (wid == 3) {
            Ks = run_fwd_chain(sh, pb, outv, lane, j0, j1,      // a_C
                               make_float2(1.f, 1.f), n2 + 1, n3);
        } else if (wid == 4) {
            Ks = run_bwd_chain(sh, pb, outv, lane, j0, j1,      // b_C
                               make_float2(1.f, 1.f), n2, n3);
        } else if (wid == 5) {
            Ks = run_fwd_chain(sh, pb, outv, lane, j0, j1,      // a_D
                               make_float2(1.f, 1.f), n3 + 1, n4);
        } else if (wid == 6) {
            Ks = run_bwd_chain(sh, pb, outv, lane, j0, j1,      // b_D
                               make_float2(1.f, 1.f), n3, n4);
        } else {
            // beta over E: t = len-1 down to n4+1
            float2 binit;
            binit.x = __expf(sh[TR + j0 * T_ + ENDT]);
            binit.y = __expf(sh[TR + j1 * T_ + ENDT]);
            Ks = run_bwd_chain(sh, pb, outv, lane, j0, j1, binit, n4, len - 1);
        }
        if (lane == 0) ((int*)(sh + RD))[16 + wid] = Ks;
    } else {
        // ===== warps 8,9: gold score (concurrent with all chains) =====
        const int*   trow = tags  + b * S_;
        const float* frow = feats + (size_t)b * (S_ * T_);
        float g = 0.0f;
        for (int t = tid - 256; t < len; t += 64) {
            const int tg = trow[t];
            const int pv = (t == 0) ? STARTT : trow[t - 1];
            g += __ldg(frow + t * T_ + tg) + sh[TR + pv * T_ + tg];
        }
        #pragma unroll
        for (int off = 16; off > 0; off >>= 1)
            g += __shfl_xor_sync(0xFFFFFFFFu, g, off);
        if (lane == 0) sh[RD + 10 + (wid - 8)] = g;
        asm volatile("bar.sync 1, 64;" ::: "memory");
        if (tid == 256) {
            const float endE = sh[TR + trow[len - 1] * T_ + ENDT];
            sh[RD + 12] = sh[RD + 10] + sh[RD + 11] + endE;
        }
    }

    __syncthreads();

    // ---- combine (warp 0), telescoped rank-1 factors (round-12-validated form):
    //  Z = (alpha.b_B)(a_B.b_C)(a_C.b_D)(a_D.beta) / (sum a_B * sum a_C * sum a_D)
    if (wid == 0) {
        const int jj = 2 * l;
        const float2 av  = *(const float2*)(sh + MV + 0 * 40 + jj);  // alpha_n1
        const float2 aB  = *(const float2*)(sh + MV + 1 * 40 + jj);
        const float2 bB  = *(const float2*)(sh + MV + 2 * 40 + jj);
        const float2 aC  = *(const float2*)(sh + MV + 3 * 40 + jj);
        const float2 bC  = *(const float2*)(sh + MV + 4 * 40 + jj);
        const float2 aD  = *(const float2*)(sh + MV + 5 * 40 + jj);
        const float2 bD  = *(const float2*)(sh + MV + 6 * 40 + jj);
        const float2 bv  = *(const float2*)(sh + MV + 7 * 40 + jj);  // beta_n4
        const bool ok = (lane < 17);
        float c1 = ok ? (av.x * bB.x + av.y * bB.y) : 0.0f;
        float c2 = ok ? (aB.x * bC.x + aB.y * bC.y) : 0.0f;
        float c3 = ok ? (aC.x * bD.x + aC.y * bD.y) : 0.0f;
        float c4 = ok ? (aD.x * bv.x + aD.y * bv.y) : 0.0f;
        float d1 = ok ? (aB.x + aB.y) : 0.0f;
        float d2 = ok ? (aC.x + aC.y) : 0.0f;
        float d3 = ok ? (aD.x + aD.y) : 0.0f;
        #pragma unroll
        for (int off = 16; off > 0; off >>= 1) {
            c1 += __shfl_xor_sync(0xFFFFFFFFu, c1, off);
            c2 += __shfl_xor_sync(0xFFFFFFFFu, c2, off);
            c3 += __shfl_xor_sync(0xFFFFFFFFu, c3, off);
            c4 += __shfl_xor_sync(0xFFFFFFFFu, c4, off);
            d1 += __shfl_xor_sync(0xFFFFFFFFu, d1, off);
            d2 += __shfl_xor_sync(0xFFFFFFFFu, d2, off);
            d3 += __shfl_xor_sync(0xFFFFFFFFu, d3, off);
        }
        if (lane == 0) {
            const int* Kp = (const int*)(sh + RD);
            const int Ks = Kp[16 + 0] + Kp[16 + 2] + Kp[16 + 4]
                         + Kp[16 + 6] + Kp[16 + 7];   // a-chain scales cancel
            const float fwd = __logf(c1) + __logf(c2) + __logf(c3) + __logf(c4)
                            - __logf(d1) - __logf(d2) - __logf(d3)
                            + (float)Ks * 0.6931471805599453f;
            g_partial[b] = fwd - sh[RD + 12];
        }
    }

    // ---- fused finalize: last block reduces all partials (deterministic) ----
    __shared__ int lastflag;
    __threadfence();
    if (tid == 0) lastflag = (atomicAdd(&g_count, 1) == B_ - 1);
    __syncthreads();
    if (lastflag) {
        __threadfence();
        volatile const float* gp = g_partial;
        if (tid < B_) sh[tid] = gp[tid];      // reuse EF region as scratch
        __syncthreads();
        #pragma unroll
        for (int off = 64; off > 0; off >>= 1) {
            if (tid < off) sh[tid] += sh[tid + off];
            __syncthreads();
        }
        if (tid == 0) {
            out[0] = sh[0] * (1.0f / (float)B_);
            g_count = 0;   // reset for next graph replay
        }
    }
}

extern "C" void kernel_launch(void* const* d_in, const int* in_sizes, int n_in,
                              void* d_out, int out_size)
{
    const float* feats = (const float*)d_in[0];
    const float* trans = (const float*)d_in[1];
    const int*   mask  = (const int*)d_in[2];
    const int*   tags  = (const int*)d_in[3];

    cudaFuncSetAttribute((const void*)crf_kernel,
                         cudaFuncAttributeMaxDynamicSharedMemorySize, SMEM_BYTES);
    crf_kernel<<<B_, NTHREADS, SMEM_BYTES>>>(feats, trans, mask, tags, (float*)d_out);
}